// round 15
// baseline (speedup 1.0000x reference)
#include <cuda_runtime.h>
#include <cuda_fp16.h>
#include <cstdint>

// ---------------------------------------------------------------------------
// Problem constants
// ---------------------------------------------------------------------------
#define NNODES_MAX 8192
#define E_MAX      131072
#define EF_MAX     (E_MAX / 2)
#define HID        768
#define PPRODS     83
#define MSG        249
#define NDIM       3

// ---------------------------------------------------------------------------
// Scratch (static __device__ BSS)
// ---------------------------------------------------------------------------
__device__ __half g_h1h[(size_t)EF_MAX * HID];   // 96 MB fp16
__device__ __half g_h2h[(size_t)EF_MAX * HID];   // 96 MB fp16
__device__ float  g_prods[(size_t)EF_MAX * PPRODS];
__device__ float  g_eaf[(size_t)EF_MAX * 6];     // compacted edge_attr
__device__ float  g_agg[NNODES_MAX * NDIM];
__device__ __half g_w2t[HID * HID];              // mW2^T [768][768] fp16
__device__ __half g_w3t[MSG * HID];              // mW3^T [249][768] fp16
__device__ int    g_fwd_src[EF_MAX];
__device__ int    g_fwd_dst[EF_MAX];
__device__ int    g_cnt;

__device__ __forceinline__ float leaky(float v) { return v > 0.f ? v : 0.01f * v; }

__device__ __forceinline__ uint32_t smem_u32(const void* p) {
    uint32_t a;
    asm("{ .reg .u64 t; cvta.to.shared.u64 t, %1; cvt.u32.u64 %0, t; }" : "=r"(a) : "l"(p));
    return a;
}

__device__ __forceinline__ void cpa16(uint32_t dst, const void* src, int valid) {
    int sz = valid ? 16 : 0;
    asm volatile("cp.async.cg.shared.global [%0], [%1], 16, %2;"
                 :: "r"(dst), "l"(src), "r"(sz));
}
__device__ __forceinline__ void cpa_commit() {
    asm volatile("cp.async.commit_group;" ::: "memory");
}
__device__ __forceinline__ void cpa_wait1() {
    asm volatile("cp.async.wait_group 1;" ::: "memory");
}

__device__ __forceinline__ void ldm_x4(uint32_t addr, uint32_t* r) {
    asm volatile("ldmatrix.sync.aligned.m8n8.x4.shared.b16 {%0,%1,%2,%3}, [%4];"
                 : "=r"(r[0]), "=r"(r[1]), "=r"(r[2]), "=r"(r[3]) : "r"(addr));
}

__device__ __forceinline__ void mma16816(float* c, const uint32_t* a, const uint32_t* b) {
    asm volatile(
        "mma.sync.aligned.m16n8k16.row.col.f32.f16.f16.f32 "
        "{%0,%1,%2,%3}, {%4,%5,%6,%7}, {%8,%9}, {%0,%1,%2,%3};"
        : "+f"(c[0]), "+f"(c[1]), "+f"(c[2]), "+f"(c[3])
        : "r"(a[0]), "r"(a[1]), "r"(a[2]), "r"(a[3]), "r"(b[0]), "r"(b[1]));
}

// ---------------------------------------------------------------------------
// k_prep: compact forward edges; gather ea; compute poly products
// ---------------------------------------------------------------------------
__global__ void k_prep(const float* __restrict__ ea,
                       const int* __restrict__ src, const int* __restrict__ dst, int E) {
    int e = blockIdx.x * blockDim.x + threadIdx.x;
    if (e >= E) return;
    int s = src[e], d = dst[e];
    if (s >= d) return;
    int i = atomicAdd(&g_cnt, 1);
    if (i >= EF_MAX) return;
    g_fwd_src[i] = s;
    g_fwd_dst[i] = d;

    float a[6];
#pragma unroll
    for (int j = 0; j < 6; j++) a[j] = ea[e * 6 + j];
#pragma unroll
    for (int j = 0; j < 6; j++) g_eaf[(size_t)i * 6 + j] = a[j];

    float* pp = g_prods + (size_t)i * PPRODS;
    int p = 0;
#pragma unroll
    for (int x = 0; x < 6; x++) pp[p++] = a[x];
#pragma unroll
    for (int x = 0; x < 6; x++)
        for (int y = x; y < 6; y++) pp[p++] = a[x] * a[y];
#pragma unroll
    for (int x = 0; x < 6; x++)
        for (int y = x; y < 6; y++)
            for (int z = y; z < 6; z++) pp[p++] = a[x] * a[y] * a[z];
}

// ---------------------------------------------------------------------------
// k_h1: h1 = fp16(leaky(ea @ W1 + b1)), vectorized half2 stores
// ---------------------------------------------------------------------------
__global__ __launch_bounds__(256) void k_h1(
    const float* __restrict__ W1, const float* __restrict__ b1, int EF)
{
    __shared__ float sW1[6 * HID];
    __shared__ float sb1[HID];
    int tid = threadIdx.x;
    for (int i = tid; i < 6 * HID; i += 256) sW1[i] = W1[i];
    for (int i = tid; i < HID;     i += 256) sb1[i] = b1[i];
    __syncthreads();

    int warp = tid >> 5, lane = tid & 31;
    int s = blockIdx.x * 8 + warp;
    if (s >= EF) return;

    float a[6];
#pragma unroll
    for (int i = 0; i < 6; i++) a[i] = g_eaf[(size_t)s * 6 + i];

    __half* h1r = g_h1h + (size_t)s * HID;
#pragma unroll
    for (int it = 0; it < HID / 64; it++) {
        int j = it * 64 + lane * 2;
        float acc0 = sb1[j];
        float acc1 = sb1[j + 1];
#pragma unroll
        for (int i = 0; i < 6; i++) {
            acc0 += a[i] * sW1[i * HID + j];
            acc1 += a[i] * sW1[i * HID + j + 1];
        }
        *(__half2*)(h1r + j) = __floats2half2_rn(leaky(acc0), leaky(acc1));
    }
}

// ---------------------------------------------------------------------------
// k_transpose2: both weight transposes in one launch (z selects tensor)
// ---------------------------------------------------------------------------
__global__ void k_transpose2(const float* __restrict__ W2, const float* __restrict__ W3)
{
    __shared__ float t[32][33];
    const int z = blockIdx.z;
    const int N = z ? MSG : HID;
    if ((int)blockIdx.x * 32 >= N) return;
    const float* W = z ? W3 : W2;
    __half* Wt = z ? g_w3t : g_w2t;

    int kb = blockIdx.y * 32, nb = blockIdx.x * 32;
    int tx = threadIdx.x, ty = threadIdx.y;
    for (int i = ty; i < 32; i += 8) {
        int k = kb + i, n = nb + tx;
        t[i][tx] = (n < N) ? W[(size_t)k * N + n] : 0.f;
    }
    __syncthreads();
    for (int i = ty; i < 32; i += 8) {
        int n = nb + i, k = kb + tx;
        if (n < N) Wt[(size_t)n * HID + k] = __float2half(t[tx][i]);
    }
}

// ---------------------------------------------------------------------------
// fp16 mma GEMM, high-occupancy: BM=BN=64, BK=32, 128 threads (4 warps,
// warp tile 32x32), 3-stage cp.async, 64B-row swizzled smem, 6 CTAs/SM.
// mode 1: C fp16 + leaky      mode 2: fused einsum + antisymmetric scatter
// ---------------------------------------------------------------------------
#define STG_B  4096               // bytes per stage per operand (64 rows x 64B)
#define NSTAGE 3
#define GEMM_SMEM_BYTES (NSTAGE * STG_B * 2)   // 24576
#define SPROD_STRIDE 84

// swizzle for 64B rows: xor 16B-unit bits [4:6) by ((row>>1)&3)
#define SWZ(row, off) ((uint32_t)((off) ^ ((((row) >> 1) & 3) << 4)))

__global__ __launch_bounds__(128, 6) void gemm_fp16(
    const __half* __restrict__ A, const __half* __restrict__ Bt,
    const float* __restrict__ bias, void* __restrict__ Cout,
    int M, int N, int K, int mode)
{
    extern __shared__ __align__(128) char smraw[];
    const uint32_t aBase = smem_u32(smraw);
    const uint32_t bBase = aBase + NSTAGE * STG_B;

    const int tid  = threadIdx.x;
    const int wid  = tid >> 5;
    const int lane = tid & 31;
    const int g    = lane >> 2;
    const int tig  = lane & 3;
    const int wm   = wid & 1;        // 0..1 -> M
    const int wn   = wid >> 1;       // 0..1 -> N
    const int row0 = blockIdx.y * 64;
    const int col0 = blockIdx.x * 64;

    // staging: thread -> row r (0..63), half-selector s (0..1), 2x 16B per op
    const int r = tid >> 1;
    const int s = tid & 1;
    const int aV = (row0 + r) < M;
    const int bV = (col0 + r) < N;
    const __half* Ag = A  + (size_t)(row0 + r) * K + s * 16;
    const __half* Bg = Bt + (size_t)(col0 + r) * K + s * 16;

    uint32_t aDst[2], bDst[2];
#pragma unroll
    for (int i = 0; i < 2; i++) {
        uint32_t off = SWZ(r, (uint32_t)(r * 64 + s * 32 + i * 16));
        aDst[i] = aBase + off;
        bDst[i] = bBase + off;
    }

    // ldmatrix addresses: FULL column offset (colp + ks*32) inside the swizzle
    uint32_t aLd[2][2], bLd[2][2];
    {
        const uint32_t aColp = (uint32_t)((lane >> 4) * 16);
        const uint32_t bColp = (uint32_t)(((lane >> 3) & 1) * 16);
#pragma unroll
        for (int mi = 0; mi < 2; mi++) {
            int rw = wm * 32 + mi * 16 + (lane & 15);
#pragma unroll
            for (int ks = 0; ks < 2; ks++)
                aLd[mi][ks] = aBase + SWZ(rw, (uint32_t)(rw * 64) + aColp + ks * 32);
        }
#pragma unroll
        for (int np = 0; np < 2; np++) {
            int rw = wn * 32 + np * 16 + (lane & 7) + ((lane >> 4) << 3);
#pragma unroll
            for (int ks = 0; ks < 2; ks++)
                bLd[np][ks] = bBase + SWZ(rw, (uint32_t)(rw * 64) + bColp + ks * 32);
        }
    }

    float acc[2][4][4];
#pragma unroll
    for (int mi = 0; mi < 2; mi++)
#pragma unroll
        for (int ni = 0; ni < 4; ni++)
#pragma unroll
            for (int q = 0; q < 4; q++) acc[mi][ni][q] = 0.f;

    const int nCh = K / 32;    // 24

    // prologue: stage chunks 0,1
#pragma unroll
    for (int c = 0; c < 2; c++) {
        uint32_t so = c * STG_B;
#pragma unroll
        for (int i = 0; i < 2; i++) {
            cpa16(aDst[i] + so, Ag + (size_t)c * 32 + i * 8, aV);
            cpa16(bDst[i] + so, Bg + (size_t)c * 32 + i * 8, bV);
        }
        cpa_commit();
    }

    for (int c = 0; c < nCh; ++c) {
        cpa_wait1();
        __syncthreads();

        if (c + 2 < nCh) {
            uint32_t so = ((c + 2) % NSTAGE) * STG_B;
#pragma unroll
            for (int i = 0; i < 2; i++) {
                cpa16(aDst[i] + so, Ag + (size_t)(c + 2) * 32 + i * 8, aV);
                cpa16(bDst[i] + so, Bg + (size_t)(c + 2) * 32 + i * 8, bV);
            }
        }
        cpa_commit();

        const uint32_t so = (c % NSTAGE) * STG_B;
#pragma unroll
        for (int ks = 0; ks < 2; ks++) {
            uint32_t a[2][4];
#pragma unroll
            for (int mi = 0; mi < 2; mi++)
                ldm_x4(aLd[mi][ks] + so, a[mi]);
            uint32_t b[2][4];
#pragma unroll
            for (int np = 0; np < 2; np++)
                ldm_x4(bLd[np][ks] + so, b[np]);
#pragma unroll
            for (int mi = 0; mi < 2; mi++)
#pragma unroll
                for (int ni = 0; ni < 4; ni++)
                    mma16816(acc[mi][ni], a[mi], b[ni >> 1] + (ni & 1) * 2);
        }
    }

    // ----------------------------- epilogues -----------------------------
    if (mode == 2) {
        __syncthreads();
        float* sprods = (float*)smraw;   // 64 x 84 floats = 21504 B
        for (int i = tid; i < 64 * PPRODS; i += 128) {
            int rr = i / PPRODS, pp = i - rr * PPRODS;
            sprods[rr * SPROD_STRIDE + pp] = g_prods[(size_t)(row0 + rr) * PPRODS + pp];
        }
        __syncthreads();

        float part[2][2][3];
#pragma unroll
        for (int mi = 0; mi < 2; mi++)
#pragma unroll
            for (int j = 0; j < 2; j++)
#pragma unroll
                for (int k = 0; k < 3; k++) part[mi][j][k] = 0.f;

#pragma unroll
        for (int mi = 0; mi < 2; mi++) {
            int rl0 = wm * 32 + mi * 16 + g;
            int rl1 = rl0 + 8;
            const float* p0 = sprods + rl0 * SPROD_STRIDE;
            const float* p1 = sprods + rl1 * SPROD_STRIDE;
#pragma unroll
            for (int ni = 0; ni < 4; ni++) {
                int cc = col0 + wn * 32 + ni * 8 + tig * 2;
                if (cc < MSG) {
                    int k = (cc >= 2 * PPRODS) ? 2 : (cc >= PPRODS ? 1 : 0);
                    int p = cc - k * PPRODS;
                    float b0 = bias[cc];
                    part[mi][0][k] += (acc[mi][ni][0] + b0) * p0[p];
                    part[mi][1][k] += (acc[mi][ni][2] + b0) * p1[p];
                }
                int c1 = cc + 1;
                if (c1 < MSG) {
                    int k = (c1 >= 2 * PPRODS) ? 2 : (c1 >= PPRODS ? 1 : 0);
                    int p = c1 - k * PPRODS;
                    float b1 = bias[c1];
                    part[mi][0][k] += (acc[mi][ni][1] + b1) * p0[p];
                    part[mi][1][k] += (acc[mi][ni][3] + b1) * p1[p];
                }
            }
        }
#pragma unroll
        for (int mi = 0; mi < 2; mi++)
#pragma unroll
            for (int j = 0; j < 2; j++)
#pragma unroll
                for (int k = 0; k < 3; k++) {
                    float v = part[mi][j][k];
                    v += __shfl_xor_sync(0xffffffffu, v, 1);
                    v += __shfl_xor_sync(0xffffffffu, v, 2);
                    part[mi][j][k] = v;
                }
        if (tig == 0) {
#pragma unroll
            for (int mi = 0; mi < 2; mi++)
#pragma unroll
                for (int j = 0; j < 2; j++) {
                    int row = row0 + wm * 32 + mi * 16 + g + j * 8;
                    if (row < M) {
                        int d  = g_fwd_dst[row];
                        int sn = g_fwd_src[row];
#pragma unroll
                        for (int k = 0; k < 3; k++) {
                            atomicAdd(&g_agg[d  * 3 + k],  part[mi][j][k]);
                            atomicAdd(&g_agg[sn * 3 + k], -part[mi][j][k]);
                        }
                    }
                }
        }
        return;
    }

    __half* Ch = (__half*)Cout;
#pragma unroll
    for (int mi = 0; mi < 2; mi++) {
        int r0 = row0 + wm * 32 + mi * 16 + g;
        int r1 = r0 + 8;
#pragma unroll
        for (int ni = 0; ni < 4; ni++) {
            int cc = col0 + wn * 32 + ni * 8 + tig * 2;
            float b0 = (cc < N)     ? bias[cc]     : 0.f;
            float b1 = (cc + 1 < N) ? bias[cc + 1] : 0.f;
            float v0 = leaky(acc[mi][ni][0] + b0);
            float v1 = leaky(acc[mi][ni][1] + b1);
            float v2 = leaky(acc[mi][ni][2] + b0);
            float v3 = leaky(acc[mi][ni][3] + b1);
            if (cc + 1 < N) {
                if (r0 < M) *(__half2*)(Ch + (size_t)r0 * N + cc) = __floats2half2_rn(v0, v1);
                if (r1 < M) *(__half2*)(Ch + (size_t)r1 * N + cc) = __floats2half2_rn(v2, v3);
            } else if (cc < N) {
                if (r0 < M) Ch[(size_t)r0 * N + cc] = __float2half(v0);
                if (r1 < M) Ch[(size_t)r1 * N + cc] = __float2half(v2);
            }
        }
    }
}

// ---------------------------------------------------------------------------
// node update: LN + MLP 19->18->17->16
// ---------------------------------------------------------------------------
__global__ __launch_bounds__(128) void k_update(
    const float* __restrict__ x,
    const float* __restrict__ ln_g, const float* __restrict__ ln_b,
    const float* __restrict__ uW1, const float* __restrict__ ub1,
    const float* __restrict__ uW2, const float* __restrict__ ub2,
    const float* __restrict__ uW3, const float* __restrict__ ub3,
    float* __restrict__ out, int N)
{
    int n = blockIdx.x * blockDim.x + threadIdx.x;
    if (n >= N) return;

    float h[19];
#pragma unroll
    for (int i = 0; i < 16; i++) h[i] = x[n * 16 + i];
#pragma unroll
    for (int k = 0; k < 3; k++) h[16 + k] = g_agg[n * 3 + k];

    float mu = 0.f;
#pragma unroll
    for (int i = 0; i < 19; i++) mu += h[i];
    mu *= (1.f / 19.f);
    float var = 0.f;
#pragma unroll
    for (int i = 0; i < 19; i++) { float d = h[i] - mu; var += d * d; }
    var *= (1.f / 19.f);
    float rstd = rsqrtf(var + 1e-5f);

    float hn[19];
#pragma unroll
    for (int i = 0; i < 19; i++) hn[i] = (h[i] - mu) * rstd * ln_g[i] + ln_b[i];

    float t1[18];
#pragma unroll
    for (int o = 0; o < 18; o++) {
        float acc = ub1[o];
#pragma unroll
        for (int i = 0; i < 19; i++) acc += hn[i] * uW1[i * 18 + o];
        t1[o] = leaky(acc);
    }
    float t2[17];
#pragma unroll
    for (int o = 0; o < 17; o++) {
        float acc = ub2[o];
#pragma unroll
        for (int i = 0; i < 18; i++) acc += t1[i] * uW2[i * 17 + o];
        t2[o] = leaky(acc);
    }
#pragma unroll
    for (int o = 0; o < 16; o++) {
        float acc = ub3[o];
#pragma unroll
        for (int i = 0; i < 17; i++) acc += t2[i] * uW3[i * 16 + o];
        out[n * 16 + o] = acc;
    }
}

// ---------------------------------------------------------------------------
// launch
// ---------------------------------------------------------------------------
extern "C" void kernel_launch(void* const* d_in, const int* in_sizes, int n_in,
                              void* d_out, int out_size)
{
    const float* x    = (const float*)d_in[0];
    const float* ea   = (const float*)d_in[1];
    const float* mW1  = (const float*)d_in[2];
    const float* mb1  = (const float*)d_in[3];
    const float* mW2  = (const float*)d_in[4];
    const float* mb2  = (const float*)d_in[5];
    const float* mW3  = (const float*)d_in[6];
    const float* mb3  = (const float*)d_in[7];
    const float* ln_g = (const float*)d_in[8];
    const float* ln_b = (const float*)d_in[9];
    const float* uW1  = (const float*)d_in[10];
    const float* ub1  = (const float*)d_in[11];
    const float* uW2  = (const float*)d_in[12];
    const float* ub2  = (const float*)d_in[13];
    const float* uW3  = (const float*)d_in[14];
    const float* ub3  = (const float*)d_in[15];
    const int*   ei   = (const int*)d_in[16];
    float* out = (float*)d_out;

    const int N  = in_sizes[0] / 16;
    const int E  = in_sizes[1] / 6;
    int EF = E / 2;
    if (EF > EF_MAX) EF = EF_MAX;

    const int* src = ei;
    const int* dst = ei + E;

    __half *p_h1, *p_h2, *p_w2t, *p_w3t;
    float  *p_agg;
    int    *p_cnt;
    cudaGetSymbolAddress((void**)&p_h1,  g_h1h);
    cudaGetSymbolAddress((void**)&p_h2,  g_h2h);
    cudaGetSymbolAddress((void**)&p_w2t, g_w2t);
    cudaGetSymbolAddress((void**)&p_w3t, g_w3t);
    cudaGetSymbolAddress((void**)&p_agg, g_agg);
    cudaGetSymbolAddress((void**)&p_cnt, g_cnt);

    cudaFuncSetAttribute(gemm_fp16, cudaFuncAttributeMaxDynamicSharedMemorySize,
                         GEMM_SMEM_BYTES);

    // launch entities 1-2: memsets
    cudaMemsetAsync(p_cnt, 0, sizeof(int), 0);
    cudaMemsetAsync(p_agg, 0, (size_t)N * NDIM * sizeof(float), 0);

    // 3: prep (compact + ea gather + prods)
    k_prep<<<(E + 255) / 256, 256>>>(ea, src, dst, E);
    // 4: h1
    k_h1<<<(EF + 7) / 8, 256>>>(mW1, mb1, EF);
    // 5: both weight transposes in one launch
    {
        dim3 blk(32, 8);
        k_transpose2<<<dim3(HID / 32, HID / 32, 2), blk>>>(mW2, mW3);
    }

    int Mtiles = (EF + 63) / 64;
    // 6: GEMM2 (profiled by ncu -s 5 -c 1)
    gemm_fp16<<<dim3(HID / 64, Mtiles), 128, GEMM_SMEM_BYTES>>>(
        p_h1, p_w2t, mb2, p_h2, EF, HID, HID, 1);
    // 7: GEMM3 fused: einsum + antisymmetric scatter
    gemm_fp16<<<dim3((MSG + 63) / 64, Mtiles), 128, GEMM_SMEM_BYTES>>>(
        p_h2, p_w3t, mb3, nullptr, EF, MSG, HID, 2);

    // 8: node update
    k_update<<<(N + 127) / 128, 128>>>(x, ln_g, ln_b, uW1, ub1, uW2, ub2, uW3, ub3, out, N);
}

// round 16
// speedup vs baseline: 1.0691x; 1.0691x over previous
#include <cuda_runtime.h>
#include <cuda_fp16.h>
#include <cstdint>

// ---------------------------------------------------------------------------
// Problem constants
// ---------------------------------------------------------------------------
#define NNODES_MAX 8192
#define E_MAX      131072
#define EF_MAX     (E_MAX / 2)
#define HID        768
#define PPRODS     83
#define MSG        249
#define NDIM       3
#define MT_MAX     (EF_MAX / 128)    // 512 m-tiles

// ---------------------------------------------------------------------------
// Scratch (static __device__ BSS)
// ---------------------------------------------------------------------------
__device__ __half g_h1h[(size_t)EF_MAX * HID];   // 96 MB fp16
__device__ __half g_h2h[(size_t)EF_MAX * HID];   // 96 MB fp16
__device__ float  g_prods[(size_t)EF_MAX * PPRODS];
__device__ float  g_eaf[(size_t)EF_MAX * 6];
__device__ float  g_agg[NNODES_MAX * NDIM];
__device__ __half g_w2t[HID * HID];              // mW2^T [768][768] fp16
__device__ __half g_w3t[MSG * HID];              // mW3^T [249][768] fp16
__device__ int    g_fwd_src[EF_MAX];
__device__ int    g_fwd_dst[EF_MAX];
__device__ int    g_ready[MT_MAX];               // per-m-tile gemm2 completion count
__device__ int    g_cnt;

__device__ __forceinline__ float leaky(float v) { return v > 0.f ? v : 0.01f * v; }

__device__ __forceinline__ uint32_t smem_u32(const void* p) {
    uint32_t a;
    asm("{ .reg .u64 t; cvta.to.shared.u64 t, %1; cvt.u32.u64 %0, t; }" : "=r"(a) : "l"(p));
    return a;
}

__device__ __forceinline__ void cpa16(uint32_t dst, const void* src, int valid) {
    int sz = valid ? 16 : 0;
    asm volatile("cp.async.cg.shared.global [%0], [%1], 16, %2;"
                 :: "r"(dst), "l"(src), "r"(sz));
}
__device__ __forceinline__ void cpa_commit() {
    asm volatile("cp.async.commit_group;" ::: "memory");
}
__device__ __forceinline__ void cpa_wait1() {
    asm volatile("cp.async.wait_group 1;" ::: "memory");
}

__device__ __forceinline__ void ldm_x4(uint32_t addr, uint32_t* r) {
    asm volatile("ldmatrix.sync.aligned.m8n8.x4.shared.b16 {%0,%1,%2,%3}, [%4];"
                 : "=r"(r[0]), "=r"(r[1]), "=r"(r[2]), "=r"(r[3]) : "r"(addr));
}

__device__ __forceinline__ void mma16816(float* c, const uint32_t* a, const uint32_t* b) {
    asm volatile(
        "mma.sync.aligned.m16n8k16.row.col.f32.f16.f16.f32 "
        "{%0,%1,%2,%3}, {%4,%5,%6,%7}, {%8,%9}, {%0,%1,%2,%3};"
        : "+f"(c[0]), "+f"(c[1]), "+f"(c[2]), "+f"(c[3])
        : "r"(a[0]), "r"(a[1]), "r"(a[2]), "r"(a[3]), "r"(b[0]), "r"(b[1]));
}

// ---------------------------------------------------------------------------
// k_prep: compact forward edges; gather ea; compute poly products
// ---------------------------------------------------------------------------
__global__ void k_prep(const float* __restrict__ ea,
                       const int* __restrict__ src, const int* __restrict__ dst, int E) {
    int e = blockIdx.x * blockDim.x + threadIdx.x;
    if (e >= E) return;
    int s = src[e], d = dst[e];
    if (s >= d) return;
    int i = atomicAdd(&g_cnt, 1);
    if (i >= EF_MAX) return;
    g_fwd_src[i] = s;
    g_fwd_dst[i] = d;

    float a[6];
#pragma unroll
    for (int j = 0; j < 6; j++) a[j] = ea[e * 6 + j];
#pragma unroll
    for (int j = 0; j < 6; j++) g_eaf[(size_t)i * 6 + j] = a[j];

    float* pp = g_prods + (size_t)i * PPRODS;
    int p = 0;
#pragma unroll
    for (int x = 0; x < 6; x++) pp[p++] = a[x];
#pragma unroll
    for (int x = 0; x < 6; x++)
        for (int y = x; y < 6; y++) pp[p++] = a[x] * a[y];
#pragma unroll
    for (int x = 0; x < 6; x++)
        for (int y = x; y < 6; y++)
            for (int z = y; z < 6; z++) pp[p++] = a[x] * a[y] * a[z];
}

// ---------------------------------------------------------------------------
// k_h1: h1 = fp16(leaky(ea @ W1 + b1))
// ---------------------------------------------------------------------------
__global__ __launch_bounds__(256) void k_h1(
    const float* __restrict__ W1, const float* __restrict__ b1, int EF)
{
    __shared__ float sW1[6 * HID];
    __shared__ float sb1[HID];
    int tid = threadIdx.x;
    for (int i = tid; i < 6 * HID; i += 256) sW1[i] = W1[i];
    for (int i = tid; i < HID;     i += 256) sb1[i] = b1[i];
    __syncthreads();

    int warp = tid >> 5, lane = tid & 31;
    int s = blockIdx.x * 8 + warp;
    if (s >= EF) return;

    float a[6];
#pragma unroll
    for (int i = 0; i < 6; i++) a[i] = g_eaf[(size_t)s * 6 + i];

    __half* h1r = g_h1h + (size_t)s * HID;
#pragma unroll
    for (int it = 0; it < HID / 64; it++) {
        int j = it * 64 + lane * 2;
        float acc0 = sb1[j];
        float acc1 = sb1[j + 1];
#pragma unroll
        for (int i = 0; i < 6; i++) {
            acc0 += a[i] * sW1[i * HID + j];
            acc1 += a[i] * sW1[i * HID + j + 1];
        }
        *(__half2*)(h1r + j) = __floats2half2_rn(leaky(acc0), leaky(acc1));
    }
}

// ---------------------------------------------------------------------------
// k_transpose2: both weight transposes in one launch (z selects tensor)
// ---------------------------------------------------------------------------
__global__ void k_transpose2(const float* __restrict__ W2, const float* __restrict__ W3)
{
    __shared__ float t[32][33];
    const int z = blockIdx.z;
    const int N = z ? MSG : HID;
    if ((int)blockIdx.x * 32 >= N) return;
    const float* W = z ? W3 : W2;
    __half* Wt = z ? g_w3t : g_w2t;

    int kb = blockIdx.y * 32, nb = blockIdx.x * 32;
    int tx = threadIdx.x, ty = threadIdx.y;
    for (int i = ty; i < 32; i += 8) {
        int k = kb + i, n = nb + tx;
        t[i][tx] = (n < N) ? W[(size_t)k * N + n] : 0.f;
    }
    __syncthreads();
    for (int i = ty; i < 32; i += 8) {
        int n = nb + i, k = kb + tx;
        if (n < N) Wt[(size_t)n * HID + k] = __float2half(t[tx][i]);
    }
}

// ---------------------------------------------------------------------------
// Persistent fused GEMM: BM=BN=128, BK=64, 3-stage cp.async, XOR-swizzled
// smem (128B rows), ldmatrix + m16n8k16. 8 warps (4M x 2N), warp tile 32x64.
// Work items: [0, nI2)  = gemm2 tiles (h2 = fp16(leaky(h1@W2+b2)), 6 n-tiles/m)
//             [nI2, tot)= gemm3 tiles (einsum+scatter, 2 n-tiles/m), gated on
//                         g_ready[mt]==6 (fence->sync->atomic release chain).
// Deadlock-free: grid <= resident CTAs; all gemm2 items precede gemm3 items
// in every CTA's round-robin sequence.
// ---------------------------------------------------------------------------
#define STG_B  16384
#define NSTAGE 3
#define GEMM_SMEM_BYTES (NSTAGE * STG_B * 2)   // 98304

__global__ __launch_bounds__(256, 2) void gemm_fused(
    const float* __restrict__ b2, const float* __restrict__ b3,
    int M, int nI2, int nTot)
{
    extern __shared__ __align__(128) char smraw[];
    const uint32_t aBase = smem_u32(smraw);
    const uint32_t bBase = aBase + NSTAGE * STG_B;

    const int tid  = threadIdx.x;
    const int wid  = tid >> 5;
    const int lane = tid & 31;
    const int g    = lane >> 2;
    const int tig  = lane & 3;
    const int wm   = wid & 3;
    const int wn   = wid >> 2;

    // thread-fixed staging / ldmatrix offsets (within a stage)
    const int r = tid >> 1;
    const int s = tid & 1;
    uint32_t aDst[4], bDst[4];
    {
        uint32_t xorv = (uint32_t)((r & 7) << 4);
#pragma unroll
        for (int i = 0; i < 4; i++) {
            uint32_t off = ((uint32_t)(r * 128 + s * 64 + i * 16)) ^ xorv;
            aDst[i] = aBase + off;
            bDst[i] = bBase + off;
        }
    }
    int aRow[2]; uint32_t aXor[2];
#pragma unroll
    for (int mi = 0; mi < 2; mi++) {
        int rw = wm * 32 + mi * 16 + (lane & 15);
        aRow[mi] = rw * 128;
        aXor[mi] = (uint32_t)((rw & 7) << 4);
    }
    const uint32_t aColp = (uint32_t)((lane >> 4) * 16);
    int bRow[4]; uint32_t bXor[4];
#pragma unroll
    for (int np = 0; np < 4; np++) {
        int rw = wn * 64 + np * 16 + (lane & 7) + ((lane >> 4) << 3);
        bRow[np] = rw * 128;
        bXor[np] = (uint32_t)((rw & 7) << 4);
    }
    const uint32_t bColp = (uint32_t)(((lane >> 3) & 1) * 16);

    for (int item = blockIdx.x; item < nTot; item += gridDim.x) {
        const int isG2 = item < nI2;
        int by, bx;
        if (isG2) { by = item / 6; bx = item - by * 6; }
        else      { int i3 = item - nI2; by = i3 >> 1; bx = i3 & 1; }
        const int row0 = by * 128;
        const int col0 = bx * 128;
        const int N = isG2 ? HID : MSG;
        const __half* A  = isG2 ? g_h1h : g_h2h;
        const __half* Bt = isG2 ? g_w2t : g_w3t;

        // gate gemm3 items on their m-tile's gemm2 completion
        if (!isG2) {
            if (tid == 0) {
                while (*(volatile int*)&g_ready[by] < 6) { }
                __threadfence();
            }
        }
        __syncthreads();   // also protects smem stage reuse across items

        const int aV = (row0 + r) < M;
        const int bV = (col0 + r) < N;
        const __half* Ag = A  + (size_t)(row0 + r) * HID + s * 32;
        const __half* Bg = Bt + (size_t)(col0 + r) * HID + s * 32;

        float acc[2][8][4];
#pragma unroll
        for (int mi = 0; mi < 2; mi++)
#pragma unroll
            for (int ni = 0; ni < 8; ni++)
#pragma unroll
                for (int q = 0; q < 4; q++) acc[mi][ni][q] = 0.f;

        const int nCh = HID / 64;   // 12

#pragma unroll
        for (int c = 0; c < 2; c++) {
            uint32_t so = c * STG_B;
#pragma unroll
            for (int i = 0; i < 4; i++) {
                cpa16(aDst[i] + so, Ag + (size_t)c * 64 + i * 8, aV);
                cpa16(bDst[i] + so, Bg + (size_t)c * 64 + i * 8, bV);
            }
            cpa_commit();
        }

        for (int c = 0; c < nCh; ++c) {
            cpa_wait1();
            __syncthreads();

            if (c + 2 < nCh) {
                uint32_t so = ((c + 2) % NSTAGE) * STG_B;
#pragma unroll
                for (int i = 0; i < 4; i++) {
                    cpa16(aDst[i] + so, Ag + (size_t)(c + 2) * 64 + i * 8, aV);
                    cpa16(bDst[i] + so, Bg + (size_t)(c + 2) * 64 + i * 8, bV);
                }
            }
            cpa_commit();

            const uint32_t so = (c % NSTAGE) * STG_B;
#pragma unroll
            for (int ks = 0; ks < 4; ks++) {
                uint32_t a[2][4];
#pragma unroll
                for (int mi = 0; mi < 2; mi++)
                    ldm_x4(aBase + so + (((uint32_t)aRow[mi] + aColp + ks * 32) ^ aXor[mi]), a[mi]);
                uint32_t b[4][4];
#pragma unroll
                for (int np = 0; np < 4; np++)
                    ldm_x4(bBase + so + (((uint32_t)bRow[np] + bColp + ks * 32) ^ bXor[np]), b[np]);
#pragma unroll
                for (int mi = 0; mi < 2; mi++)
#pragma unroll
                    for (int ni = 0; ni < 8; ni++)
                        mma16816(acc[mi][ni], a[mi], b[ni >> 1] + (ni & 1) * 2);
            }
        }

        if (isG2) {
            // epilogue: bias + leaky -> fp16 h2 (N=768, in-range)
            __half* Ch = g_h2h;
#pragma unroll
            for (int mi = 0; mi < 2; mi++) {
                int r0 = row0 + wm * 32 + mi * 16 + g;
                int r1 = r0 + 8;
#pragma unroll
                for (int ni = 0; ni < 8; ni++) {
                    int cc = col0 + wn * 64 + ni * 8 + tig * 2;
                    float c0 = b2[cc], c1 = b2[cc + 1];
                    float v0 = leaky(acc[mi][ni][0] + c0);
                    float v1 = leaky(acc[mi][ni][1] + c1);
                    float v2 = leaky(acc[mi][ni][2] + c0);
                    float v3 = leaky(acc[mi][ni][3] + c1);
                    *(__half2*)(Ch + (size_t)r0 * HID + cc) = __floats2half2_rn(v0, v1);
                    *(__half2*)(Ch + (size_t)r1 * HID + cc) = __floats2half2_rn(v2, v3);
                }
            }
            // release: make h2 visible, then signal
            __threadfence();
            __syncthreads();
            if (tid == 0) atomicAdd(&g_ready[by], 1);
        } else {
            // fused einsum + antisymmetric scatter (prods read direct-global)
            float part[2][2][3];
#pragma unroll
            for (int mi = 0; mi < 2; mi++)
#pragma unroll
                for (int j = 0; j < 2; j++)
#pragma unroll
                    for (int k = 0; k < 3; k++) part[mi][j][k] = 0.f;

#pragma unroll
            for (int mi = 0; mi < 2; mi++) {
                int r0 = row0 + wm * 32 + mi * 16 + g;
                int r1 = r0 + 8;
                const float* p0 = g_prods + (size_t)(r0 < M ? r0 : 0) * PPRODS;
                const float* p1 = g_prods + (size_t)(r1 < M ? r1 : 0) * PPRODS;
#pragma unroll
                for (int ni = 0; ni < 8; ni++) {
                    int cc = col0 + wn * 64 + ni * 8 + tig * 2;
                    if (cc < MSG) {
                        int k = (cc >= 2 * PPRODS) ? 2 : (cc >= PPRODS ? 1 : 0);
                        int p = cc - k * PPRODS;
                        float c0 = b3[cc];
                        part[mi][0][k] += (acc[mi][ni][0] + c0) * p0[p];
                        part[mi][1][k] += (acc[mi][ni][2] + c0) * p1[p];
                    }
                    int c1i = cc + 1;
                    if (c1i < MSG) {
                        int k = (c1i >= 2 * PPRODS) ? 2 : (c1i >= PPRODS ? 1 : 0);
                        int p = c1i - k * PPRODS;
                        float c1 = b3[c1i];
                        part[mi][0][k] += (acc[mi][ni][1] + c1) * p0[p];
                        part[mi][1][k] += (acc[mi][ni][3] + c1) * p1[p];
                    }
                }
            }
#pragma unroll
            for (int mi = 0; mi < 2; mi++)
#pragma unroll
                for (int j = 0; j < 2; j++)
#pragma unroll
                    for (int k = 0; k < 3; k++) {
                        float v = part[mi][j][k];
                        v += __shfl_xor_sync(0xffffffffu, v, 1);
                        v += __shfl_xor_sync(0xffffffffu, v, 2);
                        part[mi][j][k] = v;
                    }
            if (tig == 0) {
#pragma unroll
                for (int mi = 0; mi < 2; mi++)
#pragma unroll
                    for (int j = 0; j < 2; j++) {
                        int row = row0 + wm * 32 + mi * 16 + g + j * 8;
                        if (row < M) {
                            int d  = g_fwd_dst[row];
                            int sn = g_fwd_src[row];
#pragma unroll
                            for (int k = 0; k < 3; k++) {
                                atomicAdd(&g_agg[d  * 3 + k],  part[mi][j][k]);
                                atomicAdd(&g_agg[sn * 3 + k], -part[mi][j][k]);
                            }
                        }
                    }
            }
        }
    }
}

// ---------------------------------------------------------------------------
// node update: LN + MLP 19->18->17->16
// ---------------------------------------------------------------------------
__global__ __launch_bounds__(128) void k_update(
    const float* __restrict__ x,
    const float* __restrict__ ln_g, const float* __restrict__ ln_b,
    const float* __restrict__ uW1, const float* __restrict__ ub1,
    const float* __restrict__ uW2, const float* __restrict__ ub2,
    const float* __restrict__ uW3, const float* __restrict__ ub3,
    float* __restrict__ out, int N)
{
    int n = blockIdx.x * blockDim.x + threadIdx.x;
    if (n >= N) return;

    float h[19];
#pragma unroll
    for (int i = 0; i < 16; i++) h[i] = x[n * 16 + i];
#pragma unroll
    for (int k = 0; k < 3; k++) h[16 + k] = g_agg[n * 3 + k];

    float mu = 0.f;
#pragma unroll
    for (int i = 0; i < 19; i++) mu += h[i];
    mu *= (1.f / 19.f);
    float var = 0.f;
#pragma unroll
    for (int i = 0; i < 19; i++) { float d = h[i] - mu; var += d * d; }
    var *= (1.f / 19.f);
    float rstd = rsqrtf(var + 1e-5f);

    float hn[19];
#pragma unroll
    for (int i = 0; i < 19; i++) hn[i] = (h[i] - mu) * rstd * ln_g[i] + ln_b[i];

    float t1[18];
#pragma unroll
    for (int o = 0; o < 18; o++) {
        float acc = ub1[o];
#pragma unroll
        for (int i = 0; i < 19; i++) acc += hn[i] * uW1[i * 18 + o];
        t1[o] = leaky(acc);
    }
    float t2[17];
#pragma unroll
    for (int o = 0; o < 17; o++) {
        float acc = ub2[o];
#pragma unroll
        for (int i = 0; i < 18; i++) acc += t1[i] * uW2[i * 17 + o];
        t2[o] = leaky(acc);
    }
#pragma unroll
    for (int o = 0; o < 16; o++) {
        float acc = ub3[o];
#pragma unroll
        for (int i = 0; i < 17; i++) acc += t2[i] * uW3[i * 16 + o];
        out[n * 16 + o] = acc;
    }
}

// ---------------------------------------------------------------------------
// launch
// ---------------------------------------------------------------------------
extern "C" void kernel_launch(void* const* d_in, const int* in_sizes, int n_in,
                              void* d_out, int out_size)
{
    const float* x    = (const float*)d_in[0];
    const float* ea   = (const float*)d_in[1];
    const float* mW1  = (const float*)d_in[2];
    const float* mb1  = (const float*)d_in[3];
    const float* mW2  = (const float*)d_in[4];
    const float* mb2  = (const float*)d_in[5];
    const float* mW3  = (const float*)d_in[6];
    const float* mb3  = (const float*)d_in[7];
    const float* ln_g = (const float*)d_in[8];
    const float* ln_b = (const float*)d_in[9];
    const float* uW1  = (const float*)d_in[10];
    const float* ub1  = (const float*)d_in[11];
    const float* uW2  = (const float*)d_in[12];
    const float* ub2  = (const float*)d_in[13];
    const float* uW3  = (const float*)d_in[14];
    const float* ub3  = (const float*)d_in[15];
    const int*   ei   = (const int*)d_in[16];
    float* out = (float*)d_out;

    const int N  = in_sizes[0] / 16;
    const int E  = in_sizes[1] / 6;
    int EF = E / 2;
    if (EF > EF_MAX) EF = EF_MAX;

    const int* src = ei;
    const int* dst = ei + E;

    float *p_agg;
    int   *p_cnt, *p_ready;
    cudaGetSymbolAddress((void**)&p_agg,   g_agg);
    cudaGetSymbolAddress((void**)&p_cnt,   g_cnt);
    cudaGetSymbolAddress((void**)&p_ready, g_ready);

    static int grid_persist = 0;
    if (grid_persist == 0) {
        cudaFuncSetAttribute(gemm_fused, cudaFuncAttributeMaxDynamicSharedMemorySize,
                             GEMM_SMEM_BYTES);
        int sms = 148, perSM = 0;
        cudaDeviceGetAttribute(&sms, cudaDevAttrMultiProcessorCount, 0);
        cudaOccupancyMaxActiveBlocksPerMultiprocessor(&perSM, gemm_fused, 256,
                                                      GEMM_SMEM_BYTES);
        if (perSM < 1) perSM = 1;
        grid_persist = sms * perSM;
    }

    // memsets (graph-capturable memset nodes)
    cudaMemsetAsync(p_cnt, 0, sizeof(int), 0);
    cudaMemsetAsync(p_ready, 0, sizeof(int) * MT_MAX, 0);
    cudaMemsetAsync(p_agg, 0, (size_t)N * NDIM * sizeof(float), 0);

    // prep (compact + ea gather + prods)
    k_prep<<<(E + 255) / 256, 256>>>(ea, src, dst, E);
    // h1
    k_h1<<<(EF + 7) / 8, 256>>>(mW1, mb1, EF);
    // both weight transposes
    {
        dim3 blk(32, 8);
        k_transpose2<<<dim3(HID / 32, HID / 32, 2), blk>>>(mW2, mW3);
    }

    // persistent fused GEMM2 + GEMM3
    int Mtiles = (EF + 127) / 128;
    int nI2  = Mtiles * 6;
    int nTot = nI2 + Mtiles * 2;
    int grid = grid_persist < nTot ? grid_persist : nTot;
    gemm_fused<<<grid, 256, GEMM_SMEM_BYTES>>>(mb2, mb3, EF, nI2, nTot);

    // node update
    k_update<<<(N + 127) / 128, 128>>>(x, ln_g, ln_b, uW1, ub1, uW2, ub2, uW3, ub3, out, N);
}

// round 17
// speedup vs baseline: 1.1437x; 1.0698x over previous
#include <cuda_runtime.h>
#include <cuda_fp16.h>
#include <cstdint>

// ---------------------------------------------------------------------------
// Problem constants
// ---------------------------------------------------------------------------
#define NNODES_MAX 8192
#define E_MAX      131072
#define EF_MAX     (E_MAX / 2)
#define HID        768
#define PPRODS     83
#define MSG        249
#define NDIM       3

// ---------------------------------------------------------------------------
// Scratch (static __device__ BSS)
// ---------------------------------------------------------------------------
__device__ __half g_h1h[(size_t)EF_MAX * HID];   // 96 MB fp16
__device__ __half g_h2h[(size_t)EF_MAX * HID];   // 96 MB fp16
__device__ float  g_prods[(size_t)EF_MAX * PPRODS];
__device__ float  g_eaf[(size_t)EF_MAX * 6];     // compacted edge_attr
__device__ float  g_agg[NNODES_MAX * NDIM];
__device__ __half g_w2t[HID * HID];              // mW2^T [768][768] fp16
__device__ __half g_w3t[MSG * HID];              // mW3^T [249][768] fp16
__device__ int    g_fwd_src[EF_MAX];
__device__ int    g_fwd_dst[EF_MAX];
__device__ int    g_cnt;

__device__ __forceinline__ float leaky(float v) { return v > 0.f ? v : 0.01f * v; }

__device__ __forceinline__ uint32_t smem_u32(const void* p) {
    uint32_t a;
    asm("{ .reg .u64 t; cvta.to.shared.u64 t, %1; cvt.u32.u64 %0, t; }" : "=r"(a) : "l"(p));
    return a;
}

__device__ __forceinline__ void cpa16(uint32_t dst, const void* src, int valid) {
    int sz = valid ? 16 : 0;
    asm volatile("cp.async.cg.shared.global [%0], [%1], 16, %2;"
                 :: "r"(dst), "l"(src), "r"(sz));
}
__device__ __forceinline__ void cpa_commit() {
    asm volatile("cp.async.commit_group;" ::: "memory");
}
__device__ __forceinline__ void cpa_wait1() {
    asm volatile("cp.async.wait_group 1;" ::: "memory");
}

__device__ __forceinline__ void ldm_x4(uint32_t addr, uint32_t* r) {
    asm volatile("ldmatrix.sync.aligned.m8n8.x4.shared.b16 {%0,%1,%2,%3}, [%4];"
                 : "=r"(r[0]), "=r"(r[1]), "=r"(r[2]), "=r"(r[3]) : "r"(addr));
}

__device__ __forceinline__ void mma16816(float* c, const uint32_t* a, const uint32_t* b) {
    asm volatile(
        "mma.sync.aligned.m16n8k16.row.col.f32.f16.f16.f32 "
        "{%0,%1,%2,%3}, {%4,%5,%6,%7}, {%8,%9}, {%0,%1,%2,%3};"
        : "+f"(c[0]), "+f"(c[1]), "+f"(c[2]), "+f"(c[3])
        : "r"(a[0]), "r"(a[1]), "r"(a[2]), "r"(a[3]), "r"(b[0]), "r"(b[1]));
}

// ---------------------------------------------------------------------------
// k_prep: compact forward edges; gather ea; compute poly products
// ---------------------------------------------------------------------------
__global__ void k_prep(const float* __restrict__ ea,
                       const int* __restrict__ src, const int* __restrict__ dst, int E) {
    int e = blockIdx.x * blockDim.x + threadIdx.x;
    if (e >= E) return;
    int s = src[e], d = dst[e];
    if (s >= d) return;
    int i = atomicAdd(&g_cnt, 1);
    if (i >= EF_MAX) return;
    g_fwd_src[i] = s;
    g_fwd_dst[i] = d;

    float a[6];
#pragma unroll
    for (int j = 0; j < 6; j++) a[j] = ea[e * 6 + j];
#pragma unroll
    for (int j = 0; j < 6; j++) g_eaf[(size_t)i * 6 + j] = a[j];

    float* pp = g_prods + (size_t)i * PPRODS;
    int p = 0;
#pragma unroll
    for (int x = 0; x < 6; x++) pp[p++] = a[x];
#pragma unroll
    for (int x = 0; x < 6; x++)
        for (int y = x; y < 6; y++) pp[p++] = a[x] * a[y];
#pragma unroll
    for (int x = 0; x < 6; x++)
        for (int y = x; y < 6; y++)
            for (int z = y; z < 6; z++) pp[p++] = a[x] * a[y] * a[z];
}

// ---------------------------------------------------------------------------
// k_h1: h1 = fp16(leaky(ea @ W1 + b1)); warp loops over 8 edges so the
// 18KB W1/b1 smem staging is amortized 8x (64 edges per block).
// ---------------------------------------------------------------------------
#define H1_EDGES_PER_WARP 8
#define H1_EDGES_PER_BLOCK (8 * H1_EDGES_PER_WARP)   // 64

__global__ __launch_bounds__(256) void k_h1(
    const float* __restrict__ W1, const float* __restrict__ b1, int EF)
{
    __shared__ float sW1[6 * HID];
    __shared__ float sb1[HID];
    int tid = threadIdx.x;
    for (int i = tid; i < 6 * HID; i += 256) sW1[i] = W1[i];
    for (int i = tid; i < HID;     i += 256) sb1[i] = b1[i];
    __syncthreads();

    int warp = tid >> 5, lane = tid & 31;
    int s0 = blockIdx.x * H1_EDGES_PER_BLOCK + warp * H1_EDGES_PER_WARP;

#pragma unroll
    for (int eo = 0; eo < H1_EDGES_PER_WARP; eo++) {
        int s = s0 + eo;
        if (s >= EF) break;

        float a[6];
#pragma unroll
        for (int i = 0; i < 6; i++) a[i] = g_eaf[(size_t)s * 6 + i];

        __half* h1r = g_h1h + (size_t)s * HID;
#pragma unroll
        for (int it = 0; it < HID / 64; it++) {
            int j = it * 64 + lane * 2;
            float acc0 = sb1[j];
            float acc1 = sb1[j + 1];
#pragma unroll
            for (int i = 0; i < 6; i++) {
                acc0 += a[i] * sW1[i * HID + j];
                acc1 += a[i] * sW1[i * HID + j + 1];
            }
            *(__half2*)(h1r + j) = __floats2half2_rn(leaky(acc0), leaky(acc1));
        }
    }
}

// ---------------------------------------------------------------------------
// k_transpose2: both weight transposes in one launch (z selects tensor)
// ---------------------------------------------------------------------------
__global__ void k_transpose2(const float* __restrict__ W2, const float* __restrict__ W3)
{
    __shared__ float t[32][33];
    const int z = blockIdx.z;
    const int N = z ? MSG : HID;
    if ((int)blockIdx.x * 32 >= N) return;
    const float* W = z ? W3 : W2;
    __half* Wt = z ? g_w3t : g_w2t;

    int kb = blockIdx.y * 32, nb = blockIdx.x * 32;
    int tx = threadIdx.x, ty = threadIdx.y;
    for (int i = ty; i < 32; i += 8) {
        int k = kb + i, n = nb + tx;
        t[i][tx] = (n < N) ? W[(size_t)k * N + n] : 0.f;
    }
    __syncthreads();
    for (int i = ty; i < 32; i += 8) {
        int n = nb + i, k = kb + tx;
        if (n < N) Wt[(size_t)n * HID + k] = __float2half(t[tx][i]);
    }
}

// ---------------------------------------------------------------------------
// fp16 mma GEMM: BM=BN=128, BK=64, 3-stage cp.async, XOR-swizzled smem,
// ldmatrix + m16n8k16 f32 accum. 8 warps (4M x 2N), warp tile 32x64.
// mode 1: C fp16 + leaky      mode 2: fused einsum + antisymmetric scatter
// ---------------------------------------------------------------------------
#define STG_B  16384
#define NSTAGE 3
#define GEMM_SMEM_BYTES (NSTAGE * STG_B * 2)   // 98304
#define SPROD_STRIDE 84

__global__ __launch_bounds__(256, 2) void gemm_fp16(
    const __half* __restrict__ A, const __half* __restrict__ Bt,
    const float* __restrict__ bias, void* __restrict__ Cout,
    int M, int N, int K, int mode)
{
    extern __shared__ __align__(128) char smraw[];
    const uint32_t aBase = smem_u32(smraw);
    const uint32_t bBase = aBase + NSTAGE * STG_B;

    const int tid  = threadIdx.x;
    const int wid  = tid >> 5;
    const int lane = tid & 31;
    const int g    = lane >> 2;
    const int tig  = lane & 3;
    const int wm   = wid & 3;
    const int wn   = wid >> 2;
    const int row0 = blockIdx.y * 128;
    const int col0 = blockIdx.x * 128;

    const int r = tid >> 1;
    const int s = tid & 1;
    const int aV = (row0 + r) < M;
    const int bV = (col0 + r) < N;
    const __half* Ag = A  + (size_t)(row0 + r) * K + s * 32;
    const __half* Bg = Bt + (size_t)(col0 + r) * K + s * 32;

    uint32_t aDst[4], bDst[4];
    {
        uint32_t xorv = (uint32_t)((r & 7) << 4);
#pragma unroll
        for (int i = 0; i < 4; i++) {
            uint32_t off = ((uint32_t)(r * 128 + s * 64 + i * 16)) ^ xorv;
            aDst[i] = aBase + off;
            bDst[i] = bBase + off;
        }
    }

    int aRow[2]; uint32_t aXor[2];
#pragma unroll
    for (int mi = 0; mi < 2; mi++) {
        int rw = wm * 32 + mi * 16 + (lane & 15);
        aRow[mi] = rw * 128;
        aXor[mi] = (uint32_t)((rw & 7) << 4);
    }
    const uint32_t aColp = (uint32_t)((lane >> 4) * 16);
    int bRow[4]; uint32_t bXor[4];
#pragma unroll
    for (int np = 0; np < 4; np++) {
        int rw = wn * 64 + np * 16 + (lane & 7) + ((lane >> 4) << 3);
        bRow[np] = rw * 128;
        bXor[np] = (uint32_t)((rw & 7) << 4);
    }
    const uint32_t bColp = (uint32_t)(((lane >> 3) & 1) * 16);

    float acc[2][8][4];
#pragma unroll
    for (int mi = 0; mi < 2; mi++)
#pragma unroll
        for (int ni = 0; ni < 8; ni++)
#pragma unroll
            for (int q = 0; q < 4; q++) acc[mi][ni][q] = 0.f;

    const int nCh = K / 64;

#pragma unroll
    for (int c = 0; c < 2; c++) {
        uint32_t so = c * STG_B;
#pragma unroll
        for (int i = 0; i < 4; i++) {
            cpa16(aDst[i] + so, Ag + (size_t)c * 64 + i * 8, aV);
            cpa16(bDst[i] + so, Bg + (size_t)c * 64 + i * 8, bV);
        }
        cpa_commit();
    }

    for (int c = 0; c < nCh; ++c) {
        cpa_wait1();
        __syncthreads();

        if (c + 2 < nCh) {
            uint32_t so = ((c + 2) % NSTAGE) * STG_B;
#pragma unroll
            for (int i = 0; i < 4; i++) {
                cpa16(aDst[i] + so, Ag + (size_t)(c + 2) * 64 + i * 8, aV);
                cpa16(bDst[i] + so, Bg + (size_t)(c + 2) * 64 + i * 8, bV);
            }
        }
        cpa_commit();

        const uint32_t so = (c % NSTAGE) * STG_B;
#pragma unroll
        for (int ks = 0; ks < 4; ks++) {
            uint32_t a[2][4];
#pragma unroll
            for (int mi = 0; mi < 2; mi++)
                ldm_x4(aBase + so + (((uint32_t)aRow[mi] + aColp + ks * 32) ^ aXor[mi]), a[mi]);
            uint32_t b[4][4];
#pragma unroll
            for (int np = 0; np < 4; np++)
                ldm_x4(bBase + so + (((uint32_t)bRow[np] + bColp + ks * 32) ^ bXor[np]), b[np]);
#pragma unroll
            for (int mi = 0; mi < 2; mi++)
#pragma unroll
                for (int ni = 0; ni < 8; ni++)
                    mma16816(acc[mi][ni], a[mi], b[ni >> 1] + (ni & 1) * 2);
        }
    }

    // ----------------------------- epilogues -----------------------------
    if (mode == 2) {
        __syncthreads();
        float* sprods = (float*)smraw;   // 128 x 84 floats
        for (int i = tid; i < 128 * PPRODS; i += 256) {
            int rr = i / PPRODS, pp = i - rr * PPRODS;
            sprods[rr * SPROD_STRIDE + pp] = g_prods[(size_t)(row0 + rr) * PPRODS + pp];
        }
        __syncthreads();

        float part[2][2][3];
#pragma unroll
        for (int mi = 0; mi < 2; mi++)
#pragma unroll
            for (int j = 0; j < 2; j++)
#pragma unroll
                for (int k = 0; k < 3; k++) part[mi][j][k] = 0.f;

#pragma unroll
        for (int mi = 0; mi < 2; mi++) {
            int rl0 = wm * 32 + mi * 16 + g;
            int rl1 = rl0 + 8;
            const float* p0 = sprods + rl0 * SPROD_STRIDE;
            const float* p1 = sprods + rl1 * SPROD_STRIDE;
#pragma unroll
            for (int ni = 0; ni < 8; ni++) {
                int cc = col0 + wn * 64 + ni * 8 + tig * 2;
                if (cc < MSG) {
                    int k = (cc >= 2 * PPRODS) ? 2 : (cc >= PPRODS ? 1 : 0);
                    int p = cc - k * PPRODS;
                    float b0 = bias[cc];
                    part[mi][0][k] += (acc[mi][ni][0] + b0) * p0[p];
                    part[mi][1][k] += (acc[mi][ni][2] + b0) * p1[p];
                }
                int c1 = cc + 1;
                if (c1 < MSG) {
                    int k = (c1 >= 2 * PPRODS) ? 2 : (c1 >= PPRODS ? 1 : 0);
                    int p = c1 - k * PPRODS;
                    float b1 = bias[c1];
                    part[mi][0][k] += (acc[mi][ni][1] + b1) * p0[p];
                    part[mi][1][k] += (acc[mi][ni][3] + b1) * p1[p];
                }
            }
        }
#pragma unroll
        for (int mi = 0; mi < 2; mi++)
#pragma unroll
            for (int j = 0; j < 2; j++)
#pragma unroll
                for (int k = 0; k < 3; k++) {
                    float v = part[mi][j][k];
                    v += __shfl_xor_sync(0xffffffffu, v, 1);
                    v += __shfl_xor_sync(0xffffffffu, v, 2);
                    part[mi][j][k] = v;
                }
        if (tig == 0) {
#pragma unroll
            for (int mi = 0; mi < 2; mi++)
#pragma unroll
                for (int j = 0; j < 2; j++) {
                    int row = row0 + wm * 32 + mi * 16 + g + j * 8;
                    if (row < M) {
                        int d  = g_fwd_dst[row];
                        int sn = g_fwd_src[row];
#pragma unroll
                        for (int k = 0; k < 3; k++) {
                            atomicAdd(&g_agg[d  * 3 + k],  part[mi][j][k]);
                            atomicAdd(&g_agg[sn * 3 + k], -part[mi][j][k]);
                        }
                    }
                }
        }
        return;
    }

    __half* Ch = (__half*)Cout;
#pragma unroll
    for (int mi = 0; mi < 2; mi++) {
        int r0 = row0 + wm * 32 + mi * 16 + g;
        int r1 = r0 + 8;
#pragma unroll
        for (int ni = 0; ni < 8; ni++) {
            int cc = col0 + wn * 64 + ni * 8 + tig * 2;
            float b0 = (cc < N)     ? bias[cc]     : 0.f;
            float b1 = (cc + 1 < N) ? bias[cc + 1] : 0.f;
            float v0 = leaky(acc[mi][ni][0] + b0);
            float v1 = leaky(acc[mi][ni][1] + b1);
            float v2 = leaky(acc[mi][ni][2] + b0);
            float v3 = leaky(acc[mi][ni][3] + b1);
            if (cc + 1 < N) {
                if (r0 < M) *(__half2*)(Ch + (size_t)r0 * N + cc) = __floats2half2_rn(v0, v1);
                if (r1 < M) *(__half2*)(Ch + (size_t)r1 * N + cc) = __floats2half2_rn(v2, v3);
            } else if (cc < N) {
                if (r0 < M) Ch[(size_t)r0 * N + cc] = __float2half(v0);
                if (r1 < M) Ch[(size_t)r1 * N + cc] = __float2half(v2);
            }
        }
    }
}

// ---------------------------------------------------------------------------
// node update: LN + MLP 19->18->17->16
// ---------------------------------------------------------------------------
__global__ __launch_bounds__(128) void k_update(
    const float* __restrict__ x,
    const float* __restrict__ ln_g, const float* __restrict__ ln_b,
    const float* __restrict__ uW1, const float* __restrict__ ub1,
    const float* __restrict__ uW2, const float* __restrict__ ub2,
    const float* __restrict__ uW3, const float* __restrict__ ub3,
    float* __restrict__ out, int N)
{
    int n = blockIdx.x * blockDim.x + threadIdx.x;
    if (n >= N) return;

    float h[19];
#pragma unroll
    for (int i = 0; i < 16; i++) h[i] = x[n * 16 + i];
#pragma unroll
    for (int k = 0; k < 3; k++) h[16 + k] = g_agg[n * 3 + k];

    float mu = 0.f;
#pragma unroll
    for (int i = 0; i < 19; i++) mu += h[i];
    mu *= (1.f / 19.f);
    float var = 0.f;
#pragma unroll
    for (int i = 0; i < 19; i++) { float d = h[i] - mu; var += d * d; }
    var *= (1.f / 19.f);
    float rstd = rsqrtf(var + 1e-5f);

    float hn[19];
#pragma unroll
    for (int i = 0; i < 19; i++) hn[i] = (h[i] - mu) * rstd * ln_g[i] + ln_b[i];

    float t1[18];
#pragma unroll
    for (int o = 0; o < 18; o++) {
        float acc = ub1[o];
#pragma unroll
        for (int i = 0; i < 19; i++) acc += hn[i] * uW1[i * 18 + o];
        t1[o] = leaky(acc);
    }
    float t2[17];
#pragma unroll
    for (int o = 0; o < 17; o++) {
        float acc = ub2[o];
#pragma unroll
        for (int i = 0; i < 18; i++) acc += t1[i] * uW2[i * 17 + o];
        t2[o] = leaky(acc);
    }
#pragma unroll
    for (int o = 0; o < 16; o++) {
        float acc = ub3[o];
#pragma unroll
        for (int i = 0; i < 17; i++) acc += t2[i] * uW3[i * 16 + o];
        out[n * 16 + o] = acc;
    }
}

// ---------------------------------------------------------------------------
// launch
// ---------------------------------------------------------------------------
extern "C" void kernel_launch(void* const* d_in, const int* in_sizes, int n_in,
                              void* d_out, int out_size)
{
    const float* x    = (const float*)d_in[0];
    const float* ea   = (const float*)d_in[1];
    const float* mW1  = (const float*)d_in[2];
    const float* mb1  = (const float*)d_in[3];
    const float* mW2  = (const float*)d_in[4];
    const float* mb2  = (const float*)d_in[5];
    const float* mW3  = (const float*)d_in[6];
    const float* mb3  = (const float*)d_in[7];
    const float* ln_g = (const float*)d_in[8];
    const float* ln_b = (const float*)d_in[9];
    const float* uW1  = (const float*)d_in[10];
    const float* ub1  = (const float*)d_in[11];
    const float* uW2  = (const float*)d_in[12];
    const float* ub2  = (const float*)d_in[13];
    const float* uW3  = (const float*)d_in[14];
    const float* ub3  = (const float*)d_in[15];
    const int*   ei   = (const int*)d_in[16];
    float* out = (float*)d_out;

    const int N  = in_sizes[0] / 16;
    const int E  = in_sizes[1] / 6;
    int EF = E / 2;
    if (EF > EF_MAX) EF = EF_MAX;

    const int* src = ei;
    const int* dst = ei + E;

    __half *p_h1, *p_h2, *p_w2t, *p_w3t;
    float  *p_agg;
    int    *p_cnt;
    cudaGetSymbolAddress((void**)&p_h1,  g_h1h);
    cudaGetSymbolAddress((void**)&p_h2,  g_h2h);
    cudaGetSymbolAddress((void**)&p_w2t, g_w2t);
    cudaGetSymbolAddress((void**)&p_w3t, g_w3t);
    cudaGetSymbolAddress((void**)&p_agg, g_agg);
    cudaGetSymbolAddress((void**)&p_cnt, g_cnt);

    // one-time setup (first call is the uncaptured correctness run)
    static cudaStream_t s2 = nullptr;
    static cudaEvent_t evFork = nullptr, evJoin = nullptr;
    if (s2 == nullptr) {
        cudaFuncSetAttribute(gemm_fp16, cudaFuncAttributeMaxDynamicSharedMemorySize,
                             GEMM_SMEM_BYTES);
        cudaStreamCreateWithFlags(&s2, cudaStreamNonBlocking);
        cudaEventCreateWithFlags(&evFork, cudaEventDisableTiming);
        cudaEventCreateWithFlags(&evJoin, cudaEventDisableTiming);
    }

    // memsets (graph-capturable memset nodes)
    cudaMemsetAsync(p_cnt, 0, sizeof(int), 0);
    cudaMemsetAsync(p_agg, 0, (size_t)N * NDIM * sizeof(float), 0);

    // fork: weight transposes on side stream, parallel with prep + h1
    cudaEventRecord(evFork, 0);
    cudaStreamWaitEvent(s2, evFork, 0);
    {
        dim3 blk(32, 8);
        k_transpose2<<<dim3(HID / 32, HID / 32, 2), blk, 0, s2>>>(mW2, mW3);
    }
    cudaEventRecord(evJoin, s2);

    // main stream: prep (compact + ea gather + prods), then h1
    k_prep<<<(E + 255) / 256, 256>>>(ea, src, dst, E);
    k_h1<<<(EF + H1_EDGES_PER_BLOCK - 1) / H1_EDGES_PER_BLOCK, 256>>>(mW1, mb1, EF);

    // join before GEMM2 (needs both h1 and w2t)
    cudaStreamWaitEvent(0, evJoin, 0);

    int Mtiles = (EF + 127) / 128;
    // GEMM2: h2 = fp16(leaky(h1 @ W2 + b2))
    gemm_fp16<<<dim3(HID / 128, Mtiles), 256, GEMM_SMEM_BYTES>>>(
        p_h1, p_w2t, mb2, p_h2, EF, HID, HID, 1);
    // GEMM3 fused: einsum + antisymmetric scatter
    gemm_fp16<<<dim3((MSG + 127) / 128, Mtiles), 256, GEMM_SMEM_BYTES>>>(
        p_h2, p_w3t, mb3, nullptr, EF, MSG, HID, 2);

    // node update
    k_update<<<(N + 127) / 128, 128>>>(x, ln_g, ln_b, uW1, ub1, uW2, ub2, uW3, ub3, out, N);
}